// round 12
// baseline (speedup 1.0000x reference)
#include <cuda_runtime.h>
#include <cuda_bf16.h>

#define TT    512
#define BN    8192
#define NTOT  (TT * BN)          // 4,194,304
#define PAIRS (BN / 2)           // 4096
#define NC    32                 // time chunks
#define S     (TT / NC)          // 16 steps per chunk
#define Q     (S / 4)            // 4 ratio-float4 groups per chunk

#define BLK1  128                // pass1 block size (pairs)
#define GRD1  (NC * (PAIRS / BLK1))  // 1024 blocks

#define BLK   256                // pass3 block size
#define GRD   (NC * (BN / BLK))  // 1024 blocks

#define GAMMA_F 0.99f

// Scratch (device globals: allocation-free)
// g_ratio4 indexed (c*Q+q)*BN + b  ->  NC*Q*BN float4 entries (16 MB).
__device__ float4 g_ratio4[NC * Q * BN];   // [c][q][b]: 4 timesteps of elem b
__device__ float2 g_AB[NC * BN];           // {A,B} per (c,b) — L2-resident
__device__ float  g_part[2 * GRD];
__device__ unsigned int g_ctr;

// fast reciprocal: MUFU.RCP (rcp.approx), ~2.4e-7 rel err
__device__ __forceinline__ float frcp(float x) {
    float r;
    asm("rcp.approx.f32 %0, %1;" : "=f"(r) : "f"(x));
    return r;
}

// ---------------------------------------------------------------------------
// Pass 1: 2 batch elements per thread; ONE MUFU.RCP per 2 elements:
//   inv = rcp(den0*den1); rat0 = num0*den1*inv; rat1 = num1*den0*inv
// (pass1 was MUFU-bound at 1 rcp/element; this halves MUFU pipe pressure.)
// Chunk affine map composed ascending: E_exit = A*E_entry + B.
// ---------------------------------------------------------------------------
__global__ void __launch_bounds__(BLK1)
pass1(const float4* __restrict__ prob,    // [T, PAIRS]: (p0.x,p0.y,p1.x,p1.y)
      const float4* __restrict__ aprob,
      const float2* __restrict__ v,       // [T, PAIRS]
      const float2* __restrict__ rew,
      const int2*   __restrict__ act,
      const int2*   __restrict__ dn)
{
    if (blockIdx.x == 0 && threadIdx.x == 0) g_ctr = 0;

    const int c    = blockIdx.x >> 5;                         // chunk
    const int pair = ((blockIdx.x & 31) << 7) + threadIdx.x;  // 0..PAIRS-1
    const int b0   = 2 * pair;
    const int t0   = c * S;

    float A0 = 1.0f, B0 = 0.0f, A1 = 1.0f, B1 = 0.0f;
    float4 rq0, rq1;

    #pragma unroll
    for (int i = 0; i < S; i++) {
        const int idx = (t0 + i) * PAIRS + pair;

        const float4 p  = __ldcs(&prob[idx]);
        const float4 ap = __ldcs(&aprob[idx]);
        const int2   aa = __ldcs(&act[idx]);
        const int2   dd = __ldcs(&dn[idx]);
        const float2 vv = __ldg(&v[idx]);
        const float2 rr = __ldg(&rew[idx]);

        // numerators / denominators for both elements
        const float pa0  = aa.x ? p.y  : p.x;
        const float apa0 = aa.x ? ap.y : ap.x;
        const float num0 = pa0 * (ap.x + ap.y);
        const float den0 = (p.x + p.y) * apa0;

        const float pa1  = aa.y ? p.w  : p.z;
        const float apa1 = aa.y ? ap.w : ap.z;
        const float num1 = pa1 * (ap.z + ap.w);
        const float den1 = (p.z + p.w) * apa1;

        // ONE reciprocal serves both divisions
        const float inv  = frcp(den0 * den1);
        const float rat0 = num0 * den1 * inv;
        const float rat1 = num1 * den0 * inv;

        // element 0 affine step
        const float g0   = dd.x ? 0.0f : GAMMA_F;
        const float rho0 = fminf(rat0, 1.0f);
        const float At0  = rho0 * g0;
        const float Bt0  = fmaf(rho0, rr.x - vv.x, vv.x);
        B0 = fmaf(A0, Bt0, B0);          // F <- F o f_t
        A0 = A0 * At0;

        // element 1 affine step
        const float g1   = dd.y ? 0.0f : GAMMA_F;
        const float rho1 = fminf(rat1, 1.0f);
        const float At1  = rho1 * g1;
        const float Bt1  = fmaf(rho1, rr.y - vv.y, vv.y);
        B1 = fmaf(A1, Bt1, B1);
        A1 = A1 * At1;

        const float pk0 =
            __uint_as_float(__float_as_uint(rat0) | ((unsigned)dd.x << 31));
        const float pk1 =
            __uint_as_float(__float_as_uint(rat1) | ((unsigned)dd.y << 31));

        const int lane = i & 3;
        if      (lane == 0) { rq0.x = pk0; rq1.x = pk1; }
        else if (lane == 1) { rq0.y = pk0; rq1.y = pk1; }
        else if (lane == 2) { rq0.z = pk0; rq1.z = pk1; }
        else {
            rq0.w = pk0; rq1.w = pk1;
            const int base = (c * Q + (i >> 2)) * BN;
            g_ratio4[base + b0]     = rq0;      // STG.128
            g_ratio4[base + b0 + 1] = rq1;      // STG.128 (adjacent)
        }
    }

    // one float4 store covers both elements' (A,B)
    *reinterpret_cast<float4*>(&g_AB[c * BN + b0]) =
        make_float4(A0, B0, A1, B1);
}

// ---------------------------------------------------------------------------
// Pass 3 (R7/R11-identical): batched ratio loads + in-block entry-carry fold
// + replay + fused deterministic finish.
// ---------------------------------------------------------------------------
__global__ void __launch_bounds__(BLK, 6)
pass3(const float*  __restrict__ v,
      const float*  __restrict__ rew,
      const float*  __restrict__ nv,
      float*        __restrict__ out)
{
    const int c  = blockIdx.x >> 5;
    const int b  = ((blockIdx.x & 31) << 8) + threadIdx.x;
    const int t0 = c * S;

    // batched ratio loads (independent, in flight during the fold)
    float4 R[Q];
    #pragma unroll
    for (int q = 0; q < Q; q++)
        R[q] = __ldcs(&g_ratio4[(c * Q + q) * BN + b]);

    // entry carry: right-fold chunk maps NC-1 .. c+1 (L2-hot, fixed order)
    float E = __ldg(&nv[(TT - 1) * BN + b]);
    #pragma unroll 8
    for (int cc = NC - 1; cc > c; cc--) {
        const float2 ab = g_AB[cc * BN + b];
        E = fmaf(ab.x, E, ab.y);
    }

    // replay descending time; v/rew streamed (L2-warm from pass1)
    float actor = 0.0f, critic = 0.0f;
    #pragma unroll
    for (int k = 0; k < S; k++) {
        const int i   = S - 1 - k;
        const int idx = (t0 + i) * BN + b;

        const float vv = __ldg(&v[idx]);
        const float rr = __ldg(&rew[idx]);

        const float* rp = (const float*)&R[i >> 2];
        const unsigned u = __float_as_uint(rp[i & 3]);
        const float ratio = __uint_as_float(u & 0x7fffffffu);
        const float g    = (u >> 31) ? 0.0f : GAMMA_F;
        const float rho  = fminf(ratio, 1.0f);
        const float adv  = rho * (rr + g * E - vv);
        critic = fmaf(adv, adv, critic);
        const float cl = fminf(fmaxf(ratio, 0.8f), 1.2f);
        actor += fminf(ratio * adv, cl * adv);
        E = vv + adv;
    }

    // deterministic block reduction
    __shared__ float sa[8], sc[8];
    #pragma unroll
    for (int o = 16; o > 0; o >>= 1) {
        actor  += __shfl_down_sync(0xffffffffu, actor,  o);
        critic += __shfl_down_sync(0xffffffffu, critic, o);
    }
    const int w = threadIdx.x >> 5;
    if ((threadIdx.x & 31) == 0) { sa[w] = actor; sc[w] = critic; }
    __syncthreads();
    if (threadIdx.x == 0) {
        float Asum = 0.0f, Csum = 0.0f;
        #pragma unroll
        for (int k = 0; k < 8; k++) { Asum += sa[k]; Csum += sc[k]; }
        g_part[blockIdx.x]       = Asum;
        g_part[GRD + blockIdx.x] = Csum;
    }

    // last block: final deterministic reduction
    __shared__ bool is_last;
    if (threadIdx.x == 0) {
        __threadfence();
        is_last = (atomicAdd(&g_ctr, 1u) == (unsigned)(GRD - 1));
    }
    __syncthreads();
    if (is_last) {
        const int t = threadIdx.x;
        __shared__ float ra[BLK], rc[BLK];
        float Asum = 0.0f, Csum = 0.0f;
        #pragma unroll
        for (int k = 0; k < GRD / BLK; k++) {    // fixed order
            Asum += g_part[t + k * BLK];
            Csum += g_part[GRD + t + k * BLK];
        }
        ra[t] = Asum; rc[t] = Csum;
        __syncthreads();
        #pragma unroll
        for (int s = BLK / 2; s > 0; s >>= 1) {
            if (t < s) { ra[t] += ra[t + s]; rc[t] += rc[t + s]; }
            __syncthreads();
        }
        if (t == 0) {
            const float inv = 1.0f / (float)NTOT;
            out[0] = (-ra[0] + 0.5f * rc[0]) * inv;
        }
    }
}

extern "C" void kernel_launch(void* const* d_in, const int* in_sizes, int n_in,
                              void* d_out, int out_size)
{
    const float4* prob  = (const float4*)d_in[0];
    const float4* aprob = (const float4*)d_in[1];
    const float*  v     = (const float*)d_in[2];
    const float*  nv    = (const float*)d_in[3];
    const float*  rew   = (const float*)d_in[4];
    const int*    act   = (const int*)d_in[5];
    const int*    dn    = (const int*)d_in[6];
    float* out = (float*)d_out;

    pass1<<<GRD1, BLK1>>>(prob, aprob,
                          (const float2*)v, (const float2*)rew,
                          (const int2*)act, (const int2*)dn);
    pass3<<<GRD, BLK>>>(v, rew, nv, out);
}